// round 16
// baseline (speedup 1.0000x reference)
#include <cuda_runtime.h>
#include <cuda_fp16.h>
#include <cstdint>

#define NEG_SLOPE 0.1f
__device__ __forceinline__ float lrelu(float v) { return v >= 0.f ? v : NEG_SLOPE * v; }

// ---------------- static scratch ----------------
#define MAXN 50176
#define MAXE 5000000
__device__ __align__(16) __half g_xc[MAXN * 80];     // [N,80] half: 0..39 agg, 40..79 x
__device__ __align__(16) __half g_w1cat[256 * 80];   // [256,80] = [w_rel|w_root] half
__device__ __align__(16) __half g_wl[3 * 256 * 256]; // w_l1,w_l2,w_l3 half
__device__ int g_cnt[MAXN];
__device__ int g_off[MAXN + 1];
__device__ int g_cur[MAXN];
__device__ int g_esrc[MAXE];
__device__ int g_bsum[64];
__device__ int g_bbase[64];

// per-block int64-vs-int32 detection for edge_index (values < 2^31 -> odd words all 0)
__device__ __forceinline__ int block_is64(const unsigned* p, long long nwords) {
    int t = threadIdx.x;
    int odd = 0;
    if (t < 256 && (2 * t + 1) < nwords) odd = (p[2 * t + 1] != 0u);
    return !__syncthreads_or(odd);
}

// ================= fused front: count | encoder | pack | out_init =================
__global__ void fused_front(const void* __restrict__ eidx, int E,
                            const float* __restrict__ pose, const float* __restrict__ views,
                            const float* __restrict__ w_e1, const float* __restrict__ b_e1,
                            const float* __restrict__ w_e2, const float* __restrict__ b_e2,
                            const float* __restrict__ w_rel, const float* __restrict__ w_root,
                            const float* __restrict__ w_l1, const float* __restrict__ w_l2,
                            const float* __restrict__ w_l3,
                            const float* __restrict__ b_pred, float* __restrict__ out,
                            int N, int nbCnt, int nbEnc, int nbPack, int nbRnd) {
    int bx = blockIdx.x;
    int t = threadIdx.x;

    if (bx < nbCnt) {
        int is64 = block_is64((const unsigned*)eidx, 2LL * E * 2);
        int base = bx * 1024;
#pragma unroll
        for (int j = 0; j < 4; j++) {
            int e = base + t + j * 256;
            if (e < E) {
                int dst;
                if (is64) dst = (int)((const long long*)eidx)[(size_t)E + e];
                else      dst = ((const int*)eidx)[E + e];
                atomicAdd(&g_cnt[dst], 1);
            }
        }
        return;
    }
    bx -= nbCnt;

    if (bx < nbEnc) {
        __shared__ float sw1[81], sb1[9], sw2[27], sb2;
        if (t < 81) sw1[t] = w_e1[t];
        if (t < 9)  sb1[t] = b_e1[t];
        if (t >= 96 && t < 123) sw2[t - 96] = w_e2[t - 96];
        if (t == 127) sb2 = b_e2[0];
        __syncthreads();

        int n = bx * 256 + t;
        if (n >= N) return;

        __half* xo = g_xc + (size_t)n * 80 + 40;
        xo[0] = __float2half_rn(pose[n * 3 + 0]);
        xo[1] = __float2half_rn(pose[n * 3 + 1]);
        xo[2] = __float2half_rn(pose[n * 3 + 2]);

        const float* vin = views + (size_t)n * 453;

        float cur[9];
        {
            float in[3][3];
#pragma unroll
            for (int ci = 0; ci < 3; ci++)
#pragma unroll
                for (int k = 0; k < 3; k++) in[ci][k] = vin[ci * 151 + k];
#pragma unroll
            for (int c1 = 0; c1 < 9; c1++) {
                float a = sb1[c1];
#pragma unroll
                for (int ci = 0; ci < 3; ci++)
#pragma unroll
                    for (int k = 0; k < 3; k++) a += sw1[c1 * 9 + ci * 3 + k] * in[ci][k];
                cur[c1] = lrelu(a);
            }
        }
        for (int tt = 0; tt < 37; tt++) {
            float b9[9], c9[9];
#pragma unroll
            for (int which = 0; which < 2; which++) {
                int pos = 2 * tt + 1 + which;
                float in[3][3];
#pragma unroll
                for (int ci = 0; ci < 3; ci++)
#pragma unroll
                    for (int k = 0; k < 3; k++) in[ci][k] = vin[ci * 151 + 2 * pos + k];
                float* dst = which == 0 ? b9 : c9;
#pragma unroll
                for (int c1 = 0; c1 < 9; c1++) {
                    float a = sb1[c1];
#pragma unroll
                    for (int ci = 0; ci < 3; ci++)
#pragma unroll
                        for (int k = 0; k < 3; k++) a += sw1[c1 * 9 + ci * 3 + k] * in[ci][k];
                    dst[c1] = lrelu(a);
                }
            }
            float acc = sb2;
#pragma unroll
            for (int c1 = 0; c1 < 9; c1++)
                acc += cur[c1] * sw2[c1 * 3 + 0] + b9[c1] * sw2[c1 * 3 + 1] + c9[c1] * sw2[c1 * 3 + 2];
            xo[3 + tt] = __float2half_rn(lrelu(acc));
#pragma unroll
            for (int c1 = 0; c1 < 9; c1++) cur[c1] = c9[c1];
        }
        return;
    }
    bx -= nbEnc;

    if (bx < nbPack) {
        int i = bx * 256 + t;
        if (i < 256 * 80) {
            int n = i / 80, j = i % 80;
            g_w1cat[i] = __float2half_rn((j < 40) ? w_rel[n * 40 + j] : w_root[n * 40 + j - 40]);
        }
        return;
    }
    bx -= nbPack;

    if (bx < nbRnd) {
        int i = bx * 256 + t;
        if (i < 3 * 65536) {
            int which = i >> 16;
            const float* w = which == 0 ? w_l1 : (which == 1 ? w_l2 : w_l3);
            g_wl[i] = __float2half_rn(w[i & 65535]);
        }
        return;
    }
    bx -= nbRnd;

    {
        int i = bx * 256 + t;
        if (i < N) out[i] = b_pred[0];
    }
}

// ================= scan (3 kernels) =================
__device__ __forceinline__ int block_incl_scan(int v) {
    __shared__ int ws[32];
    int lane = threadIdx.x & 31, wid = threadIdx.x >> 5;
    int x = v;
#pragma unroll
    for (int o = 1; o < 32; o <<= 1) {
        int y = __shfl_up_sync(0xffffffffu, x, o);
        if (lane >= o) x += y;
    }
    if (lane == 31) ws[wid] = x;
    __syncthreads();
    if (wid == 0) {
        int s = ws[lane];
#pragma unroll
        for (int o = 1; o < 32; o <<= 1) {
            int y = __shfl_up_sync(0xffffffffu, s, o);
            if (lane >= o) s += y;
        }
        ws[lane] = s;
    }
    __syncthreads();
    int base = (wid > 0) ? ws[wid - 1] : 0;
    return base + x;
}

__global__ void scan_a(int N) {
    int i = blockIdx.x * 1024 + threadIdx.x;
    int v = (i < N) ? g_cnt[i] : 0;
    int incl = block_incl_scan(v);
    if (threadIdx.x == 1023) g_bsum[blockIdx.x] = incl;
}
__global__ void scan_b(int nblk) {
    int t = threadIdx.x;
    int v = (t < nblk) ? g_bsum[t] : 0;
    int incl = block_incl_scan(v);
    if (t < nblk) g_bbase[t] = incl - v;
}
__global__ void scan_c(int N) {
    int b = blockIdx.x;
    int i = b * 1024 + threadIdx.x;
    int v = (i < N) ? g_cnt[i] : 0;
    int incl = block_incl_scan(v);
    int excl = g_bbase[b] + incl - v;
    if (i < N) { g_off[i] = excl; g_cur[i] = excl; }
    if (i == N - 1) g_off[N] = excl + v;
}

// ================= fill =================
__global__ void fill_kernel(const void* __restrict__ eidx, int E) {
    int is64 = block_is64((const unsigned*)eidx, 2LL * E * 2);
    int base = blockIdx.x * 1024;
    int t = threadIdx.x;
#pragma unroll
    for (int j = 0; j < 4; j++) {
        int e = base + t + j * 256;
        if (e < E) {
            int src, dst;
            if (is64) {
                const long long* p = (const long long*)eidx;
                src = (int)p[e];
                dst = (int)p[(size_t)E + e];
            } else {
                const int* p = (const int*)eidx;
                src = p[e];
                dst = p[E + e];
            }
            int pos = atomicAdd(&g_cur[dst], 1);
            g_esrc[pos] = src;
        }
    }
}

// ===== gather: warp per node; lanes 0..19 each own one half2 column of x-row =====
__global__ void gather_kernel(int N) {
    int w = (blockIdx.x * blockDim.x + threadIdx.x) >> 5;
    int lane = threadIdx.x & 31;
    if (w >= N || lane >= 20) return;
    int beg = g_off[w], end = g_off[w + 1];

    float ax = 0.f, ay = 0.f;
    const __half2* xb = (const __half2*)g_xc;  // row s: half2 index s*40 + 20 + lane

    int e = beg;
    for (; e + 3 < end; e += 4) {
        int s0 = g_esrc[e], s1 = g_esrc[e + 1], s2 = g_esrc[e + 2], s3 = g_esrc[e + 3];
        __half2 v0 = xb[(size_t)s0 * 40 + 20 + lane];
        __half2 v1 = xb[(size_t)s1 * 40 + 20 + lane];
        __half2 v2 = xb[(size_t)s2 * 40 + 20 + lane];
        __half2 v3 = xb[(size_t)s3 * 40 + 20 + lane];
        float2 f0 = __half22float2(v0);
        float2 f1 = __half22float2(v1);
        float2 f2 = __half22float2(v2);
        float2 f3 = __half22float2(v3);
        ax += (f0.x + f1.x) + (f2.x + f3.x);
        ay += (f0.y + f1.y) + (f2.y + f3.y);
    }
    for (; e < end; e++) {
        float2 f = __half22float2(xb[(size_t)g_esrc[e] * 40 + 20 + lane]);
        ax += f.x;
        ay += f.y;
    }
    ((__half2*)(g_xc + (size_t)w * 80))[lane] = __floats2half2_rn(ax, ay);
}

// ================= fused MLP: per-block 128 rows through all 4 layers =================
// 1024 threads = 32 warps (4x8). Warp tile 32x32. h ping-pong in SMEM (2x64KB).
// SMEM word layout: H0 @0 (128x128w), H1 @16384, stages @32768:
//   layer1: stage s in {0,1}: A @32768+s*12288 (128x32w), B @+4096 (256x32w)
//   mid:    stage s in {0,1,2}: B @32768+s*8192 (256x32w)
// Swizzle everywhere: word col ^ ((row&7)<<2).
__device__ __forceinline__ void mma_f16(float c[4], const uint32_t a[4], const uint32_t b[2]) {
    asm volatile(
        "mma.sync.aligned.m16n8k16.row.col.f32.f16.f16.f32 "
        "{%0,%1,%2,%3}, {%4,%5,%6,%7}, {%8,%9}, {%0,%1,%2,%3};\n"
        : "+f"(c[0]), "+f"(c[1]), "+f"(c[2]), "+f"(c[3])
        : "r"(a[0]), "r"(a[1]), "r"(a[2]), "r"(a[3]), "r"(b[0]), "r"(b[1]));
}
__device__ __forceinline__ void cpasync16(uint32_t saddr, const void* g, int sz) {
    asm volatile("cp.async.cg.shared.global [%0], [%1], 16, %2;"
                 :: "r"(saddr), "l"(g), "r"(sz));
}

#define H0W 0
#define H1W 16384
#define STGW 32768
// stages max(3*8192, 2*12288) = 24576 words -> total 57344 words = 229376 B
#define MLP_SMEM_BYTES (57344 * 4)

__global__ __launch_bounds__(1024, 1)
void mlp_fused(const __half* __restrict__ xc, const __half* __restrict__ w1,
               const __half* __restrict__ wl,
               const float* __restrict__ b_rel, const float* __restrict__ b_l1,
               const float* __restrict__ b_l2, const float* __restrict__ b_l3,
               const float* __restrict__ w_pred, const float* __restrict__ b_pred,
               float* __restrict__ out, int M) {
    extern __shared__ uint32_t sm[];
    uint32_t sbase = (uint32_t)__cvta_generic_to_shared(sm);
    __shared__ float wps[256];

    int tid = threadIdx.x;
    int m0 = blockIdx.x * 128;
    int wid = tid >> 5, lane = tid & 31;
    int wm = wid >> 3, wn = wid & 7;   // 4 x 8 warp grid; warp tile 32x32
    int g = lane >> 2, t = lane & 3;
    int xg = g << 2;

    if (tid < 256) wps[tid] = w_pred[tid];

    float c[2][4][4];

    // ---------------- layer 1: A = xc (K=80), B = w1 ----------------
    {
#pragma unroll
        for (int i = 0; i < 2; i++)
#pragma unroll
            for (int j = 0; j < 4; j++)
#pragma unroll
                for (int r = 0; r < 4; r++) c[i][j][r] = 0.f;

        auto load1 = [&](int k0, int s) {
            {   // A: 128 rows x 8 blocks = 1024
                int r = tid >> 3, cq = tid & 7;
                int k = k0 + cq * 8;
                bool v = (k < 80) && (m0 + r < M);
                uint32_t so = sbase + ((STGW + s * 12288 + r * 32 + ((cq * 4) ^ ((r & 7) << 2))) << 2);
                cpasync16(so, v ? (const void*)(xc + (size_t)(m0 + r) * 80 + k) : (const void*)xc,
                          v ? 16 : 0);
            }
#pragma unroll
            for (int p = 0; p < 2; p++) {  // B: 256 rows x 8 blocks = 2048
                int lin = tid + p * 1024;
                int r = lin >> 3, cq = lin & 7;
                int k = k0 + cq * 8;
                bool v = (k < 80);
                uint32_t so = sbase + ((STGW + s * 12288 + 4096 + r * 32 + ((cq * 4) ^ ((r & 7) << 2))) << 2);
                cpasync16(so, v ? (const void*)(w1 + (size_t)r * 80 + k) : (const void*)w1,
                          v ? 16 : 0);
            }
            asm volatile("cp.async.commit_group;");
        };
        load1(0, 0);
        load1(64, 1);

        for (int i = 0; i < 2; i++) {
            if (i == 0) asm volatile("cp.async.wait_group 1;");
            else        asm volatile("cp.async.wait_group 0;");
            __syncthreads();
            const uint32_t* As = sm + STGW + i * 12288;
            const uint32_t* Bs = As + 4096;
            int nsteps = (i == 0) ? 4 : 1;
            for (int j = 0; j < nsteps; j++) {
                int c0 = (j * 8 + t) ^ xg;
                int c1 = (j * 8 + t + 4) ^ xg;
                uint32_t a[2][4], b[4][2];
#pragma unroll
                for (int mt = 0; mt < 2; mt++) {
                    int m = wm * 32 + mt * 16 + g;
                    a[mt][0] = As[m * 32 + c0];
                    a[mt][1] = As[(m + 8) * 32 + c0];
                    a[mt][2] = As[m * 32 + c1];
                    a[mt][3] = As[(m + 8) * 32 + c1];
                }
#pragma unroll
                for (int nt = 0; nt < 4; nt++) {
                    int n = wn * 32 + nt * 8 + g;
                    b[nt][0] = Bs[n * 32 + c0];
                    b[nt][1] = Bs[n * 32 + c1];
                }
#pragma unroll
                for (int mt = 0; mt < 2; mt++)
#pragma unroll
                    for (int nt = 0; nt < 4; nt++) mma_f16(c[mt][nt], a[mt], b[nt]);
            }
            __syncthreads();
        }
        // epilogue -> H0
#pragma unroll
        for (int mt = 0; mt < 2; mt++) {
            int row = wm * 32 + mt * 16 + g;
            int xr = (row & 7) << 2;
#pragma unroll
            for (int nt = 0; nt < 4; nt++) {
                int colw = wn * 16 + nt * 4 + t;
                float bx = b_rel[2 * colw], by = b_rel[2 * colw + 1];
                *(__half2*)&sm[H0W + row * 128 + (colw ^ xr)] =
                    __floats2half2_rn(lrelu(c[mt][nt][0] + bx), lrelu(c[mt][nt][1] + by));
                *(__half2*)&sm[H0W + (row + 8) * 128 + (colw ^ xr)] =
                    __floats2half2_rn(lrelu(c[mt][nt][2] + bx), lrelu(c[mt][nt][3] + by));
            }
        }
        __syncthreads();
    }

    // ---------------- mid layers: A = h_in (smem), B = weights ----------------
    auto midlayer = [&](const __half* B, const float* bias, int hinw, int houtw) {
#pragma unroll
        for (int i = 0; i < 2; i++)
#pragma unroll
            for (int j = 0; j < 4; j++)
#pragma unroll
                for (int r = 0; r < 4; r++) c[i][j][r] = 0.f;

        auto loadB = [&](int k0, int s) {
#pragma unroll
            for (int p = 0; p < 2; p++) {  // 256 rows x 8 blocks = 2048
                int lin = tid + p * 1024;
                int r = lin >> 3, cq = lin & 7;
                int k = k0 + cq * 8;
                uint32_t so = sbase + ((STGW + s * 8192 + r * 32 + ((cq * 4) ^ ((r & 7) << 2))) << 2);
                cpasync16(so, (const void*)(B + (size_t)r * 256 + k), 16);
            }
            asm volatile("cp.async.commit_group;");
        };
        loadB(0, 0);
        loadB(64, 1);

        for (int i = 0; i < 4; i++) {
            if (i + 2 < 4) {
                loadB((i + 2) * 64, (i + 2) % 3);
                asm volatile("cp.async.wait_group 2;");
            } else if (i + 1 < 4) {
                asm volatile("cp.async.wait_group 1;");
            } else {
                asm volatile("cp.async.wait_group 0;");
            }
            __syncthreads();
            const uint32_t* Bs = sm + STGW + (i % 3) * 8192;
            const uint32_t* Hin = sm + hinw;
#pragma unroll
            for (int j = 0; j < 4; j++) {
                int wb = i * 32 + j * 8;            // word col in h row (0..127)
                int hc0 = (wb + t) ^ xg;
                int hc1 = (wb + t + 4) ^ xg;
                int bc0 = (j * 8 + t) ^ xg;         // word col in B stage (0..31)
                int bc1 = (j * 8 + t + 4) ^ xg;
                uint32_t a[2][4], b[4][2];
#pragma unroll
                for (int mt = 0; mt < 2; mt++) {
                    int m = wm * 32 + mt * 16 + g;
                    a[mt][0] = Hin[m * 128 + hc0];
                    a[mt][1] = Hin[(m + 8) * 128 + hc0];
                    a[mt][2] = Hin[m * 128 + hc1];
                    a[mt][3] = Hin[(m + 8) * 128 + hc1];
                }
#pragma unroll
                for (int nt = 0; nt < 4; nt++) {
                    int n = wn * 32 + nt * 8 + g;
                    b[nt][0] = Bs[n * 32 + bc0];
                    b[nt][1] = Bs[n * 32 + bc1];
                }
#pragma unroll
                for (int mt = 0; mt < 2; mt++)
#pragma unroll
                    for (int nt = 0; nt < 4; nt++) mma_f16(c[mt][nt], a[mt], b[nt]);
            }
            __syncthreads();
        }
        // epilogue -> hout
#pragma unroll
        for (int mt = 0; mt < 2; mt++) {
            int row = wm * 32 + mt * 16 + g;
            int xr = (row & 7) << 2;
#pragma unroll
            for (int nt = 0; nt < 4; nt++) {
                int colw = wn * 16 + nt * 4 + t;
                float bx = bias[2 * colw], by = bias[2 * colw + 1];
                *(__half2*)&sm[houtw + row * 128 + (colw ^ xr)] =
                    __floats2half2_rn(lrelu(c[mt][nt][0] + bx), lrelu(c[mt][nt][1] + by));
                *(__half2*)&sm[houtw + (row + 8) * 128 + (colw ^ xr)] =
                    __floats2half2_rn(lrelu(c[mt][nt][2] + bx), lrelu(c[mt][nt][3] + by));
            }
        }
        __syncthreads();
    };

    midlayer(wl, b_l1, H0W, H1W);                 // l1': H0 -> H1
    midlayer(wl + 65536, b_l2, H1W, H0W);         // l2 : H1 -> H0
    midlayer(wl + 2 * 65536, b_l3, H0W, H1W);     // l3 : H0 -> H1

    // ---------------- pred: out[m] = H1[m,:] . w_pred + b_pred ----------------
    {
        int row = tid >> 3;       // 0..127 (8 threads per row)
        int q = tid & 7;          // 16 word-cols each
        int xr = (row & 7) << 2;
        float d = 0.f;
#pragma unroll
        for (int w = 0; w < 16; w++) {
            int colw = q * 16 + w;
            float2 f = __half22float2(*(const __half2*)&sm[H1W + row * 128 + (colw ^ xr)]);
            d += f.x * wps[2 * colw] + f.y * wps[2 * colw + 1];
        }
        d += __shfl_xor_sync(0xffffffffu, d, 1);
        d += __shfl_xor_sync(0xffffffffu, d, 2);
        d += __shfl_xor_sync(0xffffffffu, d, 4);
        if (q == 0 && m0 + row < M) out[m0 + row] = d + b_pred[0];
    }
}

extern "C" void kernel_launch(void* const* d_in, const int* in_sizes, int n_in,
                              void* d_out, int out_size) {
    const float* pose   = (const float*)d_in[0];
    const float* views  = (const float*)d_in[1];
    const void*  eidx   = d_in[2];
    const float* w_e1   = (const float*)d_in[3];
    const float* b_e1   = (const float*)d_in[4];
    const float* w_e2   = (const float*)d_in[5];
    const float* b_e2   = (const float*)d_in[6];
    const float* w_rel  = (const float*)d_in[7];
    const float* b_rel  = (const float*)d_in[8];
    const float* w_root = (const float*)d_in[9];
    const float* w_l1   = (const float*)d_in[10];
    const float* b_l1   = (const float*)d_in[11];
    const float* w_l2   = (const float*)d_in[12];
    const float* b_l2   = (const float*)d_in[13];
    const float* w_l3   = (const float*)d_in[14];
    const float* b_l3   = (const float*)d_in[15];
    const float* w_pred = (const float*)d_in[16];
    const float* b_pred = (const float*)d_in[17];
    float* out = (float*)d_out;

    int N = in_sizes[0] / 3;
    int E = in_sizes[2] / 2;

    __half *xc, *w1, *wl;
    cudaGetSymbolAddress((void**)&xc, g_xc);
    cudaGetSymbolAddress((void**)&w1, g_w1cat);
    cudaGetSymbolAddress((void**)&wl, g_wl);
    int* cnt;
    cudaGetSymbolAddress((void**)&cnt, g_cnt);

    cudaFuncSetAttribute(mlp_fused, cudaFuncAttributeMaxDynamicSharedMemorySize,
                         MLP_SMEM_BYTES);

    cudaMemsetAsync(cnt, 0, (size_t)N * sizeof(int));

    int nbCnt = (E + 1023) / 1024;
    int nbEnc = (N + 255) / 256;
    int nbPack = (256 * 80 + 255) / 256;
    int nbRnd = (3 * 65536 + 255) / 256;
    int nbOut = (N + 255) / 256;
    fused_front<<<nbCnt + nbEnc + nbPack + nbRnd + nbOut, 256>>>(
        eidx, E, pose, views, w_e1, b_e1, w_e2, b_e2,
        w_rel, w_root, w_l1, w_l2, w_l3, b_pred, out,
        N, nbCnt, nbEnc, nbPack, nbRnd);

    int nblk = (N + 1023) / 1024;
    scan_a<<<nblk, 1024>>>(N);
    scan_b<<<1, 1024>>>(nblk);
    scan_c<<<nblk, 1024>>>(N);

    fill_kernel<<<(E + 1023) / 1024, 256>>>(eidx, E);
    gather_kernel<<<(N * 32 + 255) / 256, 256>>>(N);

    mlp_fused<<<(N + 127) / 128, 1024, MLP_SMEM_BYTES>>>(
        xc, w1, wl, b_rel, b_l1, b_l2, b_l3, w_pred, b_pred, out, N);
}

// round 17
// speedup vs baseline: 1.0723x; 1.0723x over previous
#include <cuda_runtime.h>
#include <cuda_fp16.h>
#include <cstdint>

#define NEG_SLOPE 0.1f
__device__ __forceinline__ float lrelu(float v) { return v >= 0.f ? v : NEG_SLOPE * v; }

// ---------------- static scratch ----------------
#define MAXN 50176
#define MAXE 5000000
__device__ __align__(16) __half g_xc[MAXN * 80];     // [N,80] half: 0..39 agg, 40..79 x
__device__ __align__(16) __half g_w1cat[256 * 80];   // [256,80] = [w_rel|w_root] half
__device__ __align__(16) __half g_wl[3 * 256 * 256]; // w_l1,w_l2,w_l3 half
__device__ int g_cnt[MAXN];
__device__ int g_off[MAXN + 1];
__device__ int g_cur[MAXN];
__device__ int g_esrc[MAXE];
__device__ int g_bsum[64];
__device__ int g_bbase[64];

// per-block int64-vs-int32 detection for edge_index (values < 2^31 -> odd words all 0)
__device__ __forceinline__ int block_is64(const unsigned* p, long long nwords) {
    int t = threadIdx.x;
    int odd = 0;
    if (t < 256 && (2 * t + 1) < nwords) odd = (p[2 * t + 1] != 0u);
    return !__syncthreads_or(odd);
}

// ================= fused front: count | encoder | pack | out_init =================
__global__ void fused_front(const void* __restrict__ eidx, int E,
                            const float* __restrict__ pose, const float* __restrict__ views,
                            const float* __restrict__ w_e1, const float* __restrict__ b_e1,
                            const float* __restrict__ w_e2, const float* __restrict__ b_e2,
                            const float* __restrict__ w_rel, const float* __restrict__ w_root,
                            const float* __restrict__ w_l1, const float* __restrict__ w_l2,
                            const float* __restrict__ w_l3,
                            const float* __restrict__ b_pred, float* __restrict__ out,
                            int N, int nbCnt, int nbEnc, int nbPack, int nbRnd) {
    int bx = blockIdx.x;
    int t = threadIdx.x;

    if (bx < nbCnt) {
        int is64 = block_is64((const unsigned*)eidx, 2LL * E * 2);
        int base = bx * 1024;
#pragma unroll
        for (int j = 0; j < 4; j++) {
            int e = base + t + j * 256;
            if (e < E) {
                int dst;
                if (is64) dst = (int)((const long long*)eidx)[(size_t)E + e];
                else      dst = ((const int*)eidx)[E + e];
                atomicAdd(&g_cnt[dst], 1);
            }
        }
        return;
    }
    bx -= nbCnt;

    if (bx < nbEnc) {
        __shared__ float sw1[81], sb1[9], sw2[27], sb2;
        if (t < 81) sw1[t] = w_e1[t];
        if (t < 9)  sb1[t] = b_e1[t];
        if (t >= 96 && t < 123) sw2[t - 96] = w_e2[t - 96];
        if (t == 127) sb2 = b_e2[0];
        __syncthreads();

        int n = bx * 256 + t;
        if (n >= N) return;

        __half* xo = g_xc + (size_t)n * 80 + 40;
        xo[0] = __float2half_rn(pose[n * 3 + 0]);
        xo[1] = __float2half_rn(pose[n * 3 + 1]);
        xo[2] = __float2half_rn(pose[n * 3 + 2]);

        const float* vin = views + (size_t)n * 453;

        float cur[9];
        {
            float in[3][3];
#pragma unroll
            for (int ci = 0; ci < 3; ci++)
#pragma unroll
                for (int k = 0; k < 3; k++) in[ci][k] = vin[ci * 151 + k];
#pragma unroll
            for (int c1 = 0; c1 < 9; c1++) {
                float a = sb1[c1];
#pragma unroll
                for (int ci = 0; ci < 3; ci++)
#pragma unroll
                    for (int k = 0; k < 3; k++) a += sw1[c1 * 9 + ci * 3 + k] * in[ci][k];
                cur[c1] = lrelu(a);
            }
        }
        for (int tt = 0; tt < 37; tt++) {
            float b9[9], c9[9];
#pragma unroll
            for (int which = 0; which < 2; which++) {
                int pos = 2 * tt + 1 + which;
                float in[3][3];
#pragma unroll
                for (int ci = 0; ci < 3; ci++)
#pragma unroll
                    for (int k = 0; k < 3; k++) in[ci][k] = vin[ci * 151 + 2 * pos + k];
                float* dst = which == 0 ? b9 : c9;
#pragma unroll
                for (int c1 = 0; c1 < 9; c1++) {
                    float a = sb1[c1];
#pragma unroll
                    for (int ci = 0; ci < 3; ci++)
#pragma unroll
                        for (int k = 0; k < 3; k++) a += sw1[c1 * 9 + ci * 3 + k] * in[ci][k];
                    dst[c1] = lrelu(a);
                }
            }
            float acc = sb2;
#pragma unroll
            for (int c1 = 0; c1 < 9; c1++)
                acc += cur[c1] * sw2[c1 * 3 + 0] + b9[c1] * sw2[c1 * 3 + 1] + c9[c1] * sw2[c1 * 3 + 2];
            xo[3 + tt] = __float2half_rn(lrelu(acc));
#pragma unroll
            for (int c1 = 0; c1 < 9; c1++) cur[c1] = c9[c1];
        }
        return;
    }
    bx -= nbEnc;

    if (bx < nbPack) {
        int i = bx * 256 + t;
        if (i < 256 * 80) {
            int n = i / 80, j = i % 80;
            g_w1cat[i] = __float2half_rn((j < 40) ? w_rel[n * 40 + j] : w_root[n * 40 + j - 40]);
        }
        return;
    }
    bx -= nbPack;

    if (bx < nbRnd) {
        int i = bx * 256 + t;
        if (i < 3 * 65536) {
            int which = i >> 16;
            const float* w = which == 0 ? w_l1 : (which == 1 ? w_l2 : w_l3);
            g_wl[i] = __float2half_rn(w[i & 65535]);
        }
        return;
    }
    bx -= nbRnd;

    {
        int i = bx * 256 + t;
        if (i < N) out[i] = b_pred[0];
    }
}

// ================= scan (3 kernels) =================
__device__ __forceinline__ int block_incl_scan(int v) {
    __shared__ int ws[32];
    int lane = threadIdx.x & 31, wid = threadIdx.x >> 5;
    int x = v;
#pragma unroll
    for (int o = 1; o < 32; o <<= 1) {
        int y = __shfl_up_sync(0xffffffffu, x, o);
        if (lane >= o) x += y;
    }
    if (lane == 31) ws[wid] = x;
    __syncthreads();
    if (wid == 0) {
        int s = ws[lane];
#pragma unroll
        for (int o = 1; o < 32; o <<= 1) {
            int y = __shfl_up_sync(0xffffffffu, s, o);
            if (lane >= o) s += y;
        }
        ws[lane] = s;
    }
    __syncthreads();
    int base = (wid > 0) ? ws[wid - 1] : 0;
    return base + x;
}

__global__ void scan_a(int N) {
    int i = blockIdx.x * 1024 + threadIdx.x;
    int v = (i < N) ? g_cnt[i] : 0;
    int incl = block_incl_scan(v);
    if (threadIdx.x == 1023) g_bsum[blockIdx.x] = incl;
}
__global__ void scan_b(int nblk) {
    int t = threadIdx.x;
    int v = (t < nblk) ? g_bsum[t] : 0;
    int incl = block_incl_scan(v);
    if (t < nblk) g_bbase[t] = incl - v;
}
__global__ void scan_c(int N) {
    int b = blockIdx.x;
    int i = b * 1024 + threadIdx.x;
    int v = (i < N) ? g_cnt[i] : 0;
    int incl = block_incl_scan(v);
    int excl = g_bbase[b] + incl - v;
    if (i < N) { g_off[i] = excl; g_cur[i] = excl; }
    if (i == N - 1) g_off[N] = excl + v;
}

// ================= fill =================
__global__ void fill_kernel(const void* __restrict__ eidx, int E) {
    int is64 = block_is64((const unsigned*)eidx, 2LL * E * 2);
    int base = blockIdx.x * 1024;
    int t = threadIdx.x;
#pragma unroll
    for (int j = 0; j < 4; j++) {
        int e = base + t + j * 256;
        if (e < E) {
            int src, dst;
            if (is64) {
                const long long* p = (const long long*)eidx;
                src = (int)p[e];
                dst = (int)p[(size_t)E + e];
            } else {
                const int* p = (const int*)eidx;
                src = p[e];
                dst = p[E + e];
            }
            int pos = atomicAdd(&g_cur[dst], 1);
            g_esrc[pos] = src;
        }
    }
}

// ===== gather: warp per node; lanes 0..19 each own one half2 column of x-row =====
__global__ void gather_kernel(int N) {
    int w = (blockIdx.x * blockDim.x + threadIdx.x) >> 5;
    int lane = threadIdx.x & 31;
    if (w >= N || lane >= 20) return;
    int beg = g_off[w], end = g_off[w + 1];

    float ax = 0.f, ay = 0.f;
    const __half2* xb = (const __half2*)g_xc;  // row s: half2 index s*40 + 20 + lane

    int e = beg;
    for (; e + 3 < end; e += 4) {
        int s0 = g_esrc[e], s1 = g_esrc[e + 1], s2 = g_esrc[e + 2], s3 = g_esrc[e + 3];
        __half2 v0 = xb[(size_t)s0 * 40 + 20 + lane];
        __half2 v1 = xb[(size_t)s1 * 40 + 20 + lane];
        __half2 v2 = xb[(size_t)s2 * 40 + 20 + lane];
        __half2 v3 = xb[(size_t)s3 * 40 + 20 + lane];
        float2 f0 = __half22float2(v0);
        float2 f1 = __half22float2(v1);
        float2 f2 = __half22float2(v2);
        float2 f3 = __half22float2(v3);
        ax += (f0.x + f1.x) + (f2.x + f3.x);
        ay += (f0.y + f1.y) + (f2.y + f3.y);
    }
    for (; e < end; e++) {
        float2 f = __half22float2(xb[(size_t)g_esrc[e] * 40 + 20 + lane]);
        ax += f.x;
        ay += f.y;
    }
    ((__half2*)(g_xc + (size_t)w * 80))[lane] = __floats2half2_rn(ax, ay);
}

// ================= fused MLP: per-block 128 rows through all 4 layers =================
// 256 threads = 8 warps (2x4). Warp tile 64x64. h ping-pong in SMEM (2x64KB).
// SMEM word layout: H0 @0 (128x128w), H1 @16384, stages @32768:
//   layer1: stage s in {0,1}: A @32768+s*12288 (128x32w), B @+4096 (256x32w)
//   mid:    stage s in {0,1,2}: B @32768+s*8192 (256x32w)
// Swizzle everywhere: word col ^ ((row&7)<<2).
__device__ __forceinline__ void mma_f16(float c[4], const uint32_t a[4], const uint32_t b[2]) {
    asm volatile(
        "mma.sync.aligned.m16n8k16.row.col.f32.f16.f16.f32 "
        "{%0,%1,%2,%3}, {%4,%5,%6,%7}, {%8,%9}, {%0,%1,%2,%3};\n"
        : "+f"(c[0]), "+f"(c[1]), "+f"(c[2]), "+f"(c[3])
        : "r"(a[0]), "r"(a[1]), "r"(a[2]), "r"(a[3]), "r"(b[0]), "r"(b[1]));
}
__device__ __forceinline__ void cpasync16(uint32_t saddr, const void* g, int sz) {
    asm volatile("cp.async.cg.shared.global [%0], [%1], 16, %2;"
                 :: "r"(saddr), "l"(g), "r"(sz));
}

#define H0W 0
#define H1W 16384
#define STGW 32768
// stages max(3*8192, 2*12288) = 24576 words -> total 57344 words = 229376 B
#define MLP_SMEM_BYTES (57344 * 4)

__global__ __launch_bounds__(256, 1)
void mlp_fused(const __half* __restrict__ xc, const __half* __restrict__ w1,
               const __half* __restrict__ wl,
               const float* __restrict__ b_rel, const float* __restrict__ b_l1,
               const float* __restrict__ b_l2, const float* __restrict__ b_l3,
               const float* __restrict__ w_pred, const float* __restrict__ b_pred,
               float* __restrict__ out, int M) {
    extern __shared__ uint32_t sm[];
    uint32_t sbase = (uint32_t)__cvta_generic_to_shared(sm);
    __shared__ float wps[256];

    int tid = threadIdx.x;
    int m0 = blockIdx.x * 128;
    int wid = tid >> 5, lane = tid & 31;
    int wm = wid >> 2, wn = wid & 3;   // 2 x 4 warp grid; warp tile 64x64
    int g = lane >> 2, t = lane & 3;
    int xg = g << 2;

    wps[tid] = w_pred[tid];

    float c[4][8][4];

    // ---------------- layer 1: A = xc (K=80), B = w1 ----------------
    {
#pragma unroll
        for (int i = 0; i < 4; i++)
#pragma unroll
            for (int j = 0; j < 8; j++)
#pragma unroll
                for (int r = 0; r < 4; r++) c[i][j][r] = 0.f;

        auto load1 = [&](int k0, int s) {
#pragma unroll
            for (int p = 0; p < 4; p++) {  // A: 128 rows x 8 blocks = 1024
                int lin = tid + p * 256;
                int r = lin >> 3, cq = lin & 7;
                int k = k0 + cq * 8;
                bool v = (k < 80) && (m0 + r < M);
                uint32_t so = sbase + ((STGW + s * 12288 + r * 32 + ((cq * 4) ^ ((r & 7) << 2))) << 2);
                cpasync16(so, v ? (const void*)(xc + (size_t)(m0 + r) * 80 + k) : (const void*)xc,
                          v ? 16 : 0);
            }
#pragma unroll
            for (int p = 0; p < 8; p++) {  // B: 256 rows x 8 blocks = 2048
                int lin = tid + p * 256;
                int r = lin >> 3, cq = lin & 7;
                int k = k0 + cq * 8;
                bool v = (k < 80);
                uint32_t so = sbase + ((STGW + s * 12288 + 4096 + r * 32 + ((cq * 4) ^ ((r & 7) << 2))) << 2);
                cpasync16(so, v ? (const void*)(w1 + (size_t)r * 80 + k) : (const void*)w1,
                          v ? 16 : 0);
            }
            asm volatile("cp.async.commit_group;");
        };
        load1(0, 0);
        load1(64, 1);

        for (int i = 0; i < 2; i++) {
            if (i == 0) asm volatile("cp.async.wait_group 1;");
            else        asm volatile("cp.async.wait_group 0;");
            __syncthreads();
            const uint32_t* As = sm + STGW + i * 12288;
            const uint32_t* Bs = As + 4096;
            int nsteps = (i == 0) ? 4 : 1;
            for (int j = 0; j < nsteps; j++) {
                int c0 = (j * 8 + t) ^ xg;
                int c1 = (j * 8 + t + 4) ^ xg;
                uint32_t a[4][4], b[8][2];
#pragma unroll
                for (int mt = 0; mt < 4; mt++) {
                    int m = wm * 64 + mt * 16 + g;
                    a[mt][0] = As[m * 32 + c0];
                    a[mt][1] = As[(m + 8) * 32 + c0];
                    a[mt][2] = As[m * 32 + c1];
                    a[mt][3] = As[(m + 8) * 32 + c1];
                }
#pragma unroll
                for (int nt = 0; nt < 8; nt++) {
                    int n = wn * 64 + nt * 8 + g;
                    b[nt][0] = Bs[n * 32 + c0];
                    b[nt][1] = Bs[n * 32 + c1];
                }
#pragma unroll
                for (int mt = 0; mt < 4; mt++)
#pragma unroll
                    for (int nt = 0; nt < 8; nt++) mma_f16(c[mt][nt], a[mt], b[nt]);
            }
            __syncthreads();
        }
        // epilogue -> H0
#pragma unroll
        for (int mt = 0; mt < 4; mt++) {
            int row = wm * 64 + mt * 16 + g;
            int xr = (row & 7) << 2;
#pragma unroll
            for (int nt = 0; nt < 8; nt++) {
                int colw = wn * 32 + nt * 4 + t;
                float bx = b_rel[2 * colw], by = b_rel[2 * colw + 1];
                *(__half2*)&sm[H0W + row * 128 + (colw ^ xr)] =
                    __floats2half2_rn(lrelu(c[mt][nt][0] + bx), lrelu(c[mt][nt][1] + by));
                *(__half2*)&sm[H0W + (row + 8) * 128 + (colw ^ xr)] =
                    __floats2half2_rn(lrelu(c[mt][nt][2] + bx), lrelu(c[mt][nt][3] + by));
            }
        }
        __syncthreads();
    }

    // ---------------- mid layers: A = h_in (smem), B = weights ----------------
    auto midlayer = [&](const __half* B, const float* bias, int hinw, int houtw) {
#pragma unroll
        for (int i = 0; i < 4; i++)
#pragma unroll
            for (int j = 0; j < 8; j++)
#pragma unroll
                for (int r = 0; r < 4; r++) c[i][j][r] = 0.f;

        auto loadB = [&](int k0, int s) {
#pragma unroll
            for (int p = 0; p < 8; p++) {  // 256 rows x 8 blocks = 2048
                int lin = tid + p * 256;
                int r = lin >> 3, cq = lin & 7;
                int k = k0 + cq * 8;
                uint32_t so = sbase + ((STGW + s * 8192 + r * 32 + ((cq * 4) ^ ((r & 7) << 2))) << 2);
                cpasync16(so, (const void*)(B + (size_t)r * 256 + k), 16);
            }
            asm volatile("cp.async.commit_group;");
        };
        loadB(0, 0);
        loadB(64, 1);

        for (int i = 0; i < 4; i++) {
            if (i + 2 < 4) {
                loadB((i + 2) * 64, (i + 2) % 3);
                asm volatile("cp.async.wait_group 2;");
            } else if (i + 1 < 4) {
                asm volatile("cp.async.wait_group 1;");
            } else {
                asm volatile("cp.async.wait_group 0;");
            }
            __syncthreads();
            const uint32_t* Bs = sm + STGW + (i % 3) * 8192;
            const uint32_t* Hin = sm + hinw;
#pragma unroll
            for (int j = 0; j < 4; j++) {
                int wb = i * 32 + j * 8;            // word col in h row (0..127)
                int hc0 = (wb + t) ^ xg;
                int hc1 = (wb + t + 4) ^ xg;
                int bc0 = (j * 8 + t) ^ xg;         // word col in B stage (0..31)
                int bc1 = (j * 8 + t + 4) ^ xg;
                uint32_t a[4][4], b[8][2];
#pragma unroll
                for (int mt = 0; mt < 4; mt++) {
                    int m = wm * 64 + mt * 16 + g;
                    a[mt][0] = Hin[m * 128 + hc0];
                    a[mt][1] = Hin[(m + 8) * 128 + hc0];
                    a[mt][2] = Hin[m * 128 + hc1];
                    a[mt][3] = Hin[(m + 8) * 128 + hc1];
                }
#pragma unroll
                for (int nt = 0; nt < 8; nt++) {
                    int n = wn * 64 + nt * 8 + g;
                    b[nt][0] = Bs[n * 32 + bc0];
                    b[nt][1] = Bs[n * 32 + bc1];
                }
#pragma unroll
                for (int mt = 0; mt < 4; mt++)
#pragma unroll
                    for (int nt = 0; nt < 8; nt++) mma_f16(c[mt][nt], a[mt], b[nt]);
            }
            __syncthreads();
        }
        // epilogue -> hout
#pragma unroll
        for (int mt = 0; mt < 4; mt++) {
            int row = wm * 64 + mt * 16 + g;
            int xr = (row & 7) << 2;
#pragma unroll
            for (int nt = 0; nt < 8; nt++) {
                int colw = wn * 32 + nt * 4 + t;
                float bx = bias[2 * colw], by = bias[2 * colw + 1];
                *(__half2*)&sm[houtw + row * 128 + (colw ^ xr)] =
                    __floats2half2_rn(lrelu(c[mt][nt][0] + bx), lrelu(c[mt][nt][1] + by));
                *(__half2*)&sm[houtw + (row + 8) * 128 + (colw ^ xr)] =
                    __floats2half2_rn(lrelu(c[mt][nt][2] + bx), lrelu(c[mt][nt][3] + by));
            }
        }
        __syncthreads();
    };

    midlayer(wl, b_l1, H0W, H1W);                 // l1': H0 -> H1
    midlayer(wl + 65536, b_l2, H1W, H0W);         // l2 : H1 -> H0
    midlayer(wl + 2 * 65536, b_l3, H0W, H1W);     // l3 : H0 -> H1

    // ---------------- pred: out[m] = H1[m,:] . w_pred + b_pred ----------------
    {
        int row = tid >> 1;       // 0..127 (2 threads per row)
        int q = tid & 1;          // 64 word-cols each
        int xr = (row & 7) << 2;
        float d = 0.f;
#pragma unroll
        for (int w = 0; w < 64; w++) {
            int colw = q * 64 + w;
            float2 f = __half22float2(*(const __half2*)&sm[H1W + row * 128 + (colw ^ xr)]);
            d += f.x * wps[2 * colw] + f.y * wps[2 * colw + 1];
        }
        d += __shfl_xor_sync(0xffffffffu, d, 1);
        if (q == 0 && m0 + row < M) out[m0 + row] = d + b_pred[0];
    }
}

extern "C" void kernel_launch(void* const* d_in, const int* in_sizes, int n_in,
                              void* d_out, int out_size) {
    const float* pose   = (const float*)d_in[0];
    const float* views  = (const float*)d_in[1];
    const void*  eidx   = d_in[2];
    const float* w_e1   = (const float*)d_in[3];
    const float* b_e1   = (const float*)d_in[4];
    const float* w_e2   = (const float*)d_in[5];
    const float* b_e2   = (const float*)d_in[6];
    const float* w_rel  = (const float*)d_in[7];
    const float* b_rel  = (const float*)d_in[8];
    const float* w_root = (const float*)d_in[9];
    const float* w_l1   = (const float*)d_in[10];
    const float* b_l1   = (const float*)d_in[11];
    const float* w_l2   = (const float*)d_in[12];
    const float* b_l2   = (const float*)d_in[13];
    const float* w_l3   = (const float*)d_in[14];
    const float* b_l3   = (const float*)d_in[15];
    const float* w_pred = (const float*)d_in[16];
    const float* b_pred = (const float*)d_in[17];
    float* out = (float*)d_out;

    int N = in_sizes[0] / 3;
    int E = in_sizes[2] / 2;

    __half *xc, *w1, *wl;
    cudaGetSymbolAddress((void**)&xc, g_xc);
    cudaGetSymbolAddress((void**)&w1, g_w1cat);
    cudaGetSymbolAddress((void**)&wl, g_wl);
    int* cnt;
    cudaGetSymbolAddress((void**)&cnt, g_cnt);

    cudaFuncSetAttribute(mlp_fused, cudaFuncAttributeMaxDynamicSharedMemorySize,
                         MLP_SMEM_BYTES);

    cudaMemsetAsync(cnt, 0, (size_t)N * sizeof(int));

    int nbCnt = (E + 1023) / 1024;
    int nbEnc = (N + 255) / 256;
    int nbPack = (256 * 80 + 255) / 256;
    int nbRnd = (3 * 65536 + 255) / 256;
    int nbOut = (N + 255) / 256;
    fused_front<<<nbCnt + nbEnc + nbPack + nbRnd + nbOut, 256>>>(
        eidx, E, pose, views, w_e1, b_e1, w_e2, b_e2,
        w_rel, w_root, w_l1, w_l2, w_l3, b_pred, out,
        N, nbCnt, nbEnc, nbPack, nbRnd);

    int nblk = (N + 1023) / 1024;
    scan_a<<<nblk, 1024>>>(N);
    scan_b<<<1, 1024>>>(nblk);
    scan_c<<<nblk, 1024>>>(N);

    fill_kernel<<<(E + 1023) / 1024, 256>>>(eidx, E);
    gather_kernel<<<(N * 32 + 255) / 256, 256>>>(N);

    mlp_fused<<<(N + 127) / 128, 256, MLP_SMEM_BYTES>>>(
        xc, w1, wl, b_rel, b_l1, b_l2, b_l3, w_pred, b_pred, out, N);
}